// round 6
// baseline (speedup 1.0000x reference)
#include <cuda_runtime.h>

// EgoAttentionNetwork: B=8192, E=64, F_IN=7, D=64, H=4, HD=16
// One CTA per batch, 256 threads. Round-5:
//  - E=8 entity tiles (8 u64 accs): 2x FMA per weight-load wavefront.
//  - K and V GEMM passes split (regs <= 64, occupancy 4 kept).
//  - K pass emits scores via shfl (K never stored).
//  - V stored entity-major: conflict-free stores + coalesced PH7 reads.

typedef unsigned long long u64;

#define AST 68
#define VST 66
#define NTHR 256
#define FULLMASK 0xffffffffu

static __device__ __forceinline__ u64 fma2(u64 a, u64 b, u64 c) {
    u64 d;
    asm("fma.rn.f32x2 %0, %1, %2, %3;" : "=l"(d) : "l"(a), "l"(b), "l"(c));
    return d;
}
static __device__ __forceinline__ u64 add2(u64 a, u64 b) {
    u64 d;
    asm("add.rn.f32x2 %0, %1, %2;" : "=l"(d) : "l"(a), "l"(b));
    return d;
}
static __device__ __forceinline__ u64 dup2(float x) {
    u64 r;
    asm("mov.b64 %0, {%1, %1};" : "=l"(r) : "f"(x));
    return r;
}
static __device__ __forceinline__ float2 unpack2(u64 v) {
    float2 r;
    asm("mov.b64 {%0, %1}, %2;" : "=f"(r.x), "=f"(r.y) : "l"(v));
    return r;
}
static __device__ __forceinline__ void loadA8(const float* p, u64* a) {
    float4 v0 = *reinterpret_cast<const float4*>(p);
    float4 v1 = *reinterpret_cast<const float4*>(p + 4);
    asm("mov.b64 %0, {%1, %2};" : "=l"(a[0]) : "f"(v0.x), "f"(v0.y));
    asm("mov.b64 %0, {%1, %2};" : "=l"(a[1]) : "f"(v0.z), "f"(v0.w));
    asm("mov.b64 %0, {%1, %2};" : "=l"(a[2]) : "f"(v1.x), "f"(v1.y));
    asm("mov.b64 %0, {%1, %2};" : "=l"(a[3]) : "f"(v1.z), "f"(v1.w));
}

struct __align__(16) SmemT {
    float hT[64 * AST];   // hidden^T (feature-major); overlaid by sV (entity-major)
    float aT[64 * AST];   // input_all^T (feature-major)
    float sX[64 * 8];
    float h0[64];
    float sEgo[64];
    float sQ[64];
    float sO[64];
    float sS[256];
    float sP[256];
    int   sIdx[64];
    int   nOth, uniformF, egoAct;
};

__global__ void __launch_bounds__(NTHR, 4)
ego_attn_kernel(const float* __restrict__ x,
                const float* __restrict__ ego_w0, const float* __restrict__ ego_b0,
                const float* __restrict__ ego_w1, const float* __restrict__ ego_b1,
                const float* __restrict__ oth_w0, const float* __restrict__ oth_b0,
                const float* __restrict__ oth_w1, const float* __restrict__ oth_b1,
                const float* __restrict__ Wk, const float* __restrict__ Wv,
                const float* __restrict__ Wq, const float* __restrict__ Wc,
                float* __restrict__ out)
{
    __shared__ SmemT s;
    float* sV = s.hT;                      // entity-major V overlay (64 x VST <= 64 x AST)
    const int tid = threadIdx.x;
    const int b = blockIdx.x;
    const int dt2 = tid & 31;              // lane: 2 features d0, d0+1
    const int d0 = dt2 * 2;
    const int etw = tid >> 5;
    const int etr = (etw + (b & 7)) & 7;   // rotated entity-tile (8 entities each)
    const float* xb = x + b * 448;

    // ---- PH1: load x, init scores ----
    for (int idx = tid; idx < 448; idx += NTHR) {
        int e = idx / 7, f = idx % 7;
        s.sX[e * 8 + f] = __ldg(xb + idx);
    }
    s.sS[tid] = -1e30f;
    __syncthreads();

    // ---- PH2: compaction (warp0) | ego layer0 (warp1) ----
    if (tid < 32) {
        const int lane = tid;
        int egoA = (s.sX[0] >= 0.5f) ? 1 : 0;
        unsigned m1 = __ballot_sync(FULLMASK, (lane >= 1) && (s.sX[lane * 8] >= 0.5f));
        unsigned m2 = __ballot_sync(FULLMASK, s.sX[(lane + 32) * 8] >= 0.5f);
        int cnt = __popc(m1) + __popc(m2);
        unsigned lmask = (1u << lane) - 1u;
        if (cnt == 0 && !egoA) {
            s.sIdx[lane] = lane + 1;
            if (lane < 31) s.sIdx[lane + 32] = lane + 33;
            if (lane == 0) { s.nOth = 63; s.uniformF = 1; s.egoAct = egoA; }
        } else {
            if ((lane >= 1) && (m1 >> lane & 1u))
                s.sIdx[__popc(m1 & lmask)] = lane;
            if (m2 >> lane & 1u)
                s.sIdx[__popc(m1) + __popc(m2 & lmask)] = lane + 32;
            if (lane == 0) { s.nOth = cnt; s.uniformF = 0; s.egoAct = egoA; }
        }
    } else if (tid < 64) {
        const int lane = tid - 32;
        #pragma unroll
        for (int r = 0; r < 2; r++) {
            int d = lane + r * 32;
            float acc = __ldg(ego_b0 + d);
            #pragma unroll
            for (int f = 0; f < 7; f++)
                acc += s.sX[f] * __ldg(ego_w0 + f * 64 + d);
            s.h0[d] = fmaxf(acc, 0.f);
        }
    }
    __syncthreads();

    const int nOth = s.nOth;
    const int uniformF = s.uniformF;
    const int egoAct = s.egoAct;
    const int cEgo = nOth;
    const int nTot = nOth + 1;
    int PAD8 = (nTot + 7) & ~7; if (PAD8 > 64) PAD8 = 64;
    const int nT8 = PAD8 >> 3;
    const bool gact = (etr < nT8);
    const int e0 = etr * 8;

    // ---- PH3: others layer0 (192 thr) | ego layer1 (64 thr) ----
    if (tid < 192) {
        const int total = nOth * 32;
        for (int idx = tid; idx < total; idx += 192) {
            int i = idx >> 5, dd = (idx & 31) * 2;
            int e = s.sIdx[i];
            const float* xr = s.sX + e * 8;
            float2 bb = *reinterpret_cast<const float2*>(oth_b0 + dd);
            float ax = bb.x, ay = bb.y;
            #pragma unroll
            for (int f = 0; f < 7; f++) {
                float2 w = __ldg(reinterpret_cast<const float2*>(oth_w0 + f * 64 + dd));
                float xv = xr[f];
                ax += xv * w.x; ay += xv * w.y;
            }
            s.hT[dd * AST + i]       = fmaxf(ax, 0.f);
            s.hT[(dd + 1) * AST + i] = fmaxf(ay, 0.f);
        }
    } else {
        const int d = tid - 192;
        float a0 = __ldg(ego_b1 + d), a1 = 0.f, a2 = 0.f, a3 = 0.f;
        #pragma unroll 8
        for (int k = 0; k < 64; k += 4) {
            a0 += s.h0[k]     * __ldg(ego_w1 + (k)     * 64 + d);
            a1 += s.h0[k + 1] * __ldg(ego_w1 + (k + 1) * 64 + d);
            a2 += s.h0[k + 2] * __ldg(ego_w1 + (k + 2) * 64 + d);
            a3 += s.h0[k + 3] * __ldg(ego_w1 + (k + 3) * 64 + d);
        }
        s.sEgo[d] = fmaxf((a0 + a1) + (a2 + a3), 0.f);
    }
    if (tid < 64) {
        for (int c = nOth; c < PAD8; c++) s.hT[tid * AST + c] = 0.f;
    }
    __syncthreads();

    // ---- PH4: layer1 GEMM hT->aT (E=8, bias+relu+ego patch); free warps: q ----
    if (gact) {
        u64 acc0[4] = {0, 0, 0, 0}, acc1[4] = {0, 0, 0, 0};
        #pragma unroll 4
        for (int k = 0; k < 64; k++) {
            u64 pA[4]; loadA8(s.hT + k * AST + e0, pA);
            float2 w = __ldg(reinterpret_cast<const float2*>(oth_w1 + k * 64 + d0));
            u64 wx = dup2(w.x), wy = dup2(w.y);
            #pragma unroll
            for (int j = 0; j < 4; j++) {
                acc0[j] = fma2(pA[j], wx, acc0[j]);
                acc1[j] = fma2(pA[j], wy, acc1[j]);
            }
        }
        float b0v = __ldg(oth_b1 + d0);
        float b1v = __ldg(oth_b1 + d0 + 1);
        float eg0 = s.sEgo[d0], eg1 = s.sEgo[d0 + 1];
        float r0[8], r1[8];
        #pragma unroll
        for (int j = 0; j < 4; j++) {
            float2 c0 = unpack2(acc0[j]);
            float2 c1 = unpack2(acc1[j]);
            r0[2 * j] = fmaxf(c0.x + b0v, 0.f);  r0[2 * j + 1] = fmaxf(c0.y + b0v, 0.f);
            r1[2 * j] = fmaxf(c1.x + b1v, 0.f);  r1[2 * j + 1] = fmaxf(c1.y + b1v, 0.f);
        }
        #pragma unroll
        for (int m = 0; m < 8; m++) {
            if (e0 + m == cEgo) { r0[m] = eg0; r1[m] = eg1; }
        }
        *reinterpret_cast<float4*>(s.aT + d0 * AST + e0) =
            make_float4(r0[0], r0[1], r0[2], r0[3]);
        *reinterpret_cast<float4*>(s.aT + d0 * AST + e0 + 4) =
            make_float4(r0[4], r0[5], r0[6], r0[7]);
        *reinterpret_cast<float4*>(s.aT + (d0 + 1) * AST + e0) =
            make_float4(r1[0], r1[1], r1[2], r1[3]);
        *reinterpret_cast<float4*>(s.aT + (d0 + 1) * AST + e0 + 4) =
            make_float4(r1[4], r1[5], r1[6], r1[7]);
    }
    const bool canFreeQ = (nT8 <= 6);
    if (canFreeQ && etr >= nT8 && (etr - nT8) < 2) {
        const int d = (etr - nT8) * 32 + dt2;
        float a0 = 0.f, a1 = 0.f, a2 = 0.f, a3 = 0.f;
        #pragma unroll 8
        for (int k = 0; k < 64; k += 4) {
            a0 += s.sEgo[k]     * __ldg(Wq + (k)     * 64 + d);
            a1 += s.sEgo[k + 1] * __ldg(Wq + (k + 1) * 64 + d);
            a2 += s.sEgo[k + 2] * __ldg(Wq + (k + 2) * 64 + d);
            a3 += s.sEgo[k + 3] * __ldg(Wq + (k + 3) * 64 + d);
        }
        s.sQ[d] = (a0 + a1) + (a2 + a3);
    }
    __syncthreads();
    if (!canFreeQ) {
        if (tid < 64) {
            const int d = tid;
            float a0 = 0.f, a1 = 0.f, a2 = 0.f, a3 = 0.f;
            #pragma unroll 8
            for (int k = 0; k < 64; k += 4) {
                a0 += s.sEgo[k]     * __ldg(Wq + (k)     * 64 + d);
                a1 += s.sEgo[k + 1] * __ldg(Wq + (k + 1) * 64 + d);
                a2 += s.sEgo[k + 2] * __ldg(Wq + (k + 2) * 64 + d);
                a3 += s.sEgo[k + 3] * __ldg(Wq + (k + 3) * 64 + d);
            }
            s.sQ[d] = (a0 + a1) + (a2 + a3);
        }
        __syncthreads();
    }

    // ---- PH5: K GEMM (scores via shfl), then V GEMM (entity-major store) ----
    if (gact) {
        // K pass
        {
            u64 acc0[4] = {0, 0, 0, 0}, acc1[4] = {0, 0, 0, 0};
            #pragma unroll 4
            for (int k = 0; k < 64; k++) {
                u64 pA[4]; loadA8(s.aT + k * AST + e0, pA);
                float2 w = __ldg(reinterpret_cast<const float2*>(Wk + k * 64 + d0));
                u64 wx = dup2(w.x), wy = dup2(w.y);
                #pragma unroll
                for (int j = 0; j < 4; j++) {
                    acc0[j] = fma2(pA[j], wx, acc0[j]);
                    acc1[j] = fma2(pA[j], wy, acc1[j]);
                }
            }
            u64 q0 = dup2(s.sQ[d0]), q1 = dup2(s.sQ[d0 + 1]);
            u64 sj[4];
            #pragma unroll
            for (int j = 0; j < 4; j++)
                sj[j] = fma2(acc0[j], q0, fma2(acc1[j], q1, (u64)0));
            // reduce over the 8 lanes (16 features) of this head
            #pragma unroll
            for (int o = 1; o < 8; o <<= 1) {
                #pragma unroll
                for (int j = 0; j < 4; j++)
                    sj[j] = add2(sj[j], __shfl_xor_sync(FULLMASK, sj[j], o));
            }
            if ((dt2 & 7) == 0) {
                const int h = dt2 >> 3;
                float sc[8];
                #pragma unroll
                for (int j = 0; j < 4; j++) {
                    float2 f = unpack2(sj[j]);
                    sc[2 * j] = f.x; sc[2 * j + 1] = f.y;
                }
                #pragma unroll
                for (int m = 0; m < 8; m++) {
                    int col = e0 + m;
                    bool act = uniformF ? (col < nTot)
                                        : ((col < nOth) || (col == cEgo && egoAct));
                    s.sS[h * 64 + col] = act ? sc[m] * 0.25f : -1e30f;
                }
            }
        }
        // V pass
        {
            u64 acc0[4] = {0, 0, 0, 0}, acc1[4] = {0, 0, 0, 0};
            #pragma unroll 4
            for (int k = 0; k < 64; k++) {
                u64 pA[4]; loadA8(s.aT + k * AST + e0, pA);
                float2 w = __ldg(reinterpret_cast<const float2*>(Wv + k * 64 + d0));
                u64 wx = dup2(w.x), wy = dup2(w.y);
                #pragma unroll
                for (int j = 0; j < 4; j++) {
                    acc0[j] = fma2(pA[j], wx, acc0[j]);
                    acc1[j] = fma2(pA[j], wy, acc1[j]);
                }
            }
            #pragma unroll
            for (int j = 0; j < 4; j++) {
                float2 a = unpack2(acc0[j]);   // V[2j], V[2j+1] at feature d0
                float2 c = unpack2(acc1[j]);   // at feature d0+1
                *reinterpret_cast<float2*>(sV + (e0 + 2 * j) * VST + d0) =
                    make_float2(a.x, c.x);
                *reinterpret_cast<float2*>(sV + (e0 + 2 * j + 1) * VST + d0) =
                    make_float2(a.y, c.y);
            }
        }
    }
    __syncthreads();

    // ---- PH6: softmax per head (warps 0-3) ----
    if (tid < 128) {
        const int h = tid >> 5, lane = tid & 31;
        if (uniformF) {
            const float p = 1.0f / 64.0f;
            s.sP[h * 64 + lane] = p;
            s.sP[h * 64 + lane + 32] = p;
        } else {
            float s0 = s.sS[h * 64 + lane];
            float s1 = s.sS[h * 64 + lane + 32];
            float m = fmaxf(s0, s1);
            #pragma unroll
            for (int off = 16; off; off >>= 1)
                m = fmaxf(m, __shfl_xor_sync(FULLMASK, m, off));
            float e0v = __expf(s0 - m);
            float e1v = __expf(s1 - m);
            float sum = e0v + e1v;
            #pragma unroll
            for (int off = 16; off; off >>= 1)
                sum += __shfl_xor_sync(FULLMASK, sum, off);
            float inv = 1.0f / sum;
            s.sP[h * 64 + lane] = e0v * inv;
            s.sP[h * 64 + lane + 32] = e1v * inv;
        }
    }
    __syncthreads();

    // ---- PH7: attention-weighted sum (V entity-major, coalesced) ----
    if (tid < 64) {
        const int d = tid, h = d >> 4;
        const float* pr = s.sP + h * 64;
        float a0 = 0.f, a1 = 0.f, a2 = 0.f, a3 = 0.f;
        for (int e = 0; e < PAD8; e += 4) {
            a0 += pr[e]     * sV[(e)     * VST + d];
            a1 += pr[e + 1] * sV[(e + 1) * VST + d];
            a2 += pr[e + 2] * sV[(e + 2) * VST + d];
            a3 += pr[e + 3] * sV[(e + 3) * VST + d];
        }
        s.sO[d] = (a0 + a1) + (a2 + a3);
    }
    __syncthreads();

    // ---- PH8: epilogue (out @ Wc + ego) * 0.5 ----
    if (tid < 64) {
        const int d = tid;
        float a0 = 0.f, a1 = 0.f, a2 = 0.f, a3 = 0.f;
        #pragma unroll 8
        for (int k = 0; k < 64; k += 4) {
            a0 += s.sO[k]     * __ldg(Wc + (k)     * 64 + d);
            a1 += s.sO[k + 1] * __ldg(Wc + (k + 1) * 64 + d);
            a2 += s.sO[k + 2] * __ldg(Wc + (k + 2) * 64 + d);
            a3 += s.sO[k + 3] * __ldg(Wc + (k + 3) * 64 + d);
        }
        out[b * 64 + d] = (((a0 + a1) + (a2 + a3)) + s.sEgo[d]) * 0.5f;
    }
}

extern "C" void kernel_launch(void* const* d_in, const int* in_sizes, int n_in,
                              void* d_out, int out_size) {
    (void)in_sizes; (void)n_in; (void)out_size;
    const float* x      = (const float*)d_in[0];
    const float* ego_w0 = (const float*)d_in[1];
    const float* ego_b0 = (const float*)d_in[2];
    const float* ego_w1 = (const float*)d_in[3];
    const float* ego_b1 = (const float*)d_in[4];
    const float* oth_w0 = (const float*)d_in[5];
    const float* oth_b0 = (const float*)d_in[6];
    const float* oth_w1 = (const float*)d_in[7];
    const float* oth_b1 = (const float*)d_in[8];
    const float* Wk     = (const float*)d_in[9];
    const float* Wv     = (const float*)d_in[10];
    const float* Wq     = (const float*)d_in[11];
    const float* Wc     = (const float*)d_in[12];
    float* out = (float*)d_out;

    ego_attn_kernel<<<8192, NTHR>>>(x, ego_w0, ego_b0, ego_w1, ego_b1,
                                    oth_w0, oth_b0, oth_w1, oth_b1,
                                    Wk, Wv, Wq, Wc, out);
}